// round 1
// baseline (speedup 1.0000x reference)
#include <cuda_runtime.h>

// Fused GAT representation network, fp32 baseline.
// One block of 256 threads processes ITEMS=2 graphs (16 nodes each) entirely
// in shared memory. Grid = B/2 blocks.

#define NN 16          // nodes per graph
#define STRIDE 260     // shared row stride in floats (multiple of 4 for float4)

__device__ __forceinline__ unsigned adjmask(int i) {
    int r = i >> 2, c = i & 3;
    unsigned m = 1u << i;          // self loop
    if (c > 0) m |= 1u << (i - 1);
    if (c < 3) m |= 1u << (i + 1);
    if (r > 0) m |= 1u << (i - 4);
    if (r < 3) m |= 1u << (i + 4);
    return m;
}

struct Smem {
    float h[2][NN * STRIDE];   // node features / wh ping (33280 B)
    float alpha[2][NN * 68];   // attention coeffs [i][h(pad17)][j]; also x staging (8704 B)
    float esrc[2][NN][4];
    float edst[2][NN][4];
    float g[2][64];
    float y[2][132];
    float red[2][8];
};

template<int FIN, bool FINAL>
__device__ __forceinline__ void gat_layer(
    Smem& s, int t,
    const float* __restrict__ W,
    const float* __restrict__ asrc,
    const float* __restrict__ adst,
    const float* __restrict__ bb)
{
    // ---- wh = h @ W : thread t owns output column t (head h = t/64) ----
    float acc[2][NN];
    #pragma unroll
    for (int u = 0; u < 2; u++)
        #pragma unroll
        for (int n = 0; n < NN; n++) acc[u][n] = 0.f;

    #pragma unroll 4
    for (int k = 0; k < FIN; k += 4) {
        float w0 = W[(k + 0) * 256 + t];
        float w1 = W[(k + 1) * 256 + t];
        float w2 = W[(k + 2) * 256 + t];
        float w3 = W[(k + 3) * 256 + t];
        #pragma unroll
        for (int u = 0; u < 2; u++) {
            #pragma unroll
            for (int n = 0; n < NN; n++) {
                float4 hv = *(const float4*)&s.h[u][n * STRIDE + k];  // broadcast LDS
                acc[u][n] = fmaf(hv.x, w0, fmaf(hv.y, w1,
                              fmaf(hv.z, w2, fmaf(hv.w, w3, acc[u][n]))));
            }
        }
    }
    __syncthreads();
    // overwrite input features with wh
    #pragma unroll
    for (int u = 0; u < 2; u++)
        #pragma unroll
        for (int n = 0; n < NN; n++) s.h[u][n * STRIDE + t] = acc[u][n];
    __syncthreads();

    // ---- per-(node, head) attention logits: e_src, e_dst ----
    if (t < 128) {
        int u = t >> 6, id = t & 63, n = id & 15, h = id >> 4;
        float as = 0.f, ad = 0.f;
        #pragma unroll 8
        for (int c = 0; c < 64; c++) {
            float v = s.h[u][n * STRIDE + h * 64 + c];
            as = fmaf(v, asrc[h * 64 + c], as);
            ad = fmaf(v, adst[h * 64 + c], ad);
        }
        s.esrc[u][n][h] = as;
        s.edst[u][n][h] = ad;
    }
    __syncthreads();

    // ---- masked softmax over the 4-connected grid + self loops ----
    if (t < 128) {
        int u = t >> 6, id = t & 63, i = id & 15, h = id >> 4;
        unsigned m = adjmask(i);
        float ed = s.edst[u][i][h];
        float eb[NN];
        float mx = -1e30f;
        #pragma unroll
        for (int j = 0; j < NN; j++) {
            eb[j] = -1e30f;
            if ((m >> j) & 1u) {
                float e = ed + s.esrc[u][j][h];
                e = e > 0.f ? e : 0.2f * e;     // leaky relu, slope 0.2
                eb[j] = e;
                mx = fmaxf(mx, e);
            }
        }
        float ssum = 0.f;
        #pragma unroll
        for (int j = 0; j < NN; j++) {
            float a = ((m >> j) & 1u) ? __expf(eb[j] - mx) : 0.f;
            eb[j] = a;
            ssum += a;
        }
        float inv = 1.f / ssum;
        #pragma unroll
        for (int j = 0; j < NN; j++)
            s.alpha[u][i * 68 + h * 17 + j] = eb[j] * inv;
    }
    __syncthreads();

    // ---- aggregation: out[i][t] = sum_j alpha[i][h][j] * wh[j][t] ----
    int h = t >> 6;
    float o[2][NN];
    #pragma unroll
    for (int u = 0; u < 2; u++)
        #pragma unroll
        for (int i = 0; i < NN; i++) o[u][i] = 0.f;
    #pragma unroll
    for (int j = 0; j < NN; j++) {
        float wv0 = s.h[0][j * STRIDE + t];
        float wv1 = s.h[1][j * STRIDE + t];
        #pragma unroll
        for (int i = 0; i < NN; i++) {
            o[0][i] = fmaf(s.alpha[0][i * 68 + h * 17 + j], wv0, o[0][i]);
            o[1][i] = fmaf(s.alpha[1][i * 68 + h * 17 + j], wv1, o[1][i]);
        }
    }
    __syncthreads();
    if (FINAL) {
        // raw per-head outputs; head-mean + bias folded into pooling later
        #pragma unroll
        for (int u = 0; u < 2; u++)
            #pragma unroll
            for (int i = 0; i < NN; i++) s.h[u][i * STRIDE + t] = o[u][i];
    } else {
        float bv = bb[t];
        #pragma unroll
        for (int u = 0; u < 2; u++)
            #pragma unroll
            for (int i = 0; i < NN; i++)
                s.h[u][i * STRIDE + t] = fmaxf(o[u][i] + bv, 0.f);
    }
    __syncthreads();
}

__global__ void __launch_bounds__(256, 2) gat_fused_kernel(
    const float* __restrict__ x,
    const float* __restrict__ w_in, const float* __restrict__ b_in,
    const float* __restrict__ W0, const float* __restrict__ as0,
    const float* __restrict__ ad0, const float* __restrict__ bb0,
    const float* __restrict__ W1, const float* __restrict__ as1,
    const float* __restrict__ ad1, const float* __restrict__ bb1,
    const float* __restrict__ W2, const float* __restrict__ as2,
    const float* __restrict__ ad2, const float* __restrict__ bb2,
    const float* __restrict__ w1, const float* __restrict__ b1,
    const float* __restrict__ lng, const float* __restrict__ lnb,
    const float* __restrict__ w2, const float* __restrict__ b2,
    float* __restrict__ out)
{
    __shared__ Smem s;
    int t = threadIdx.x;
    long item0 = (long)blockIdx.x * 2;

    // ---- stage x (2 graphs * 256 floats) into alpha scratch ----
    s.alpha[0][t] = x[item0 * 256 + t];
    s.alpha[1][t] = x[item0 * 256 + 256 + t];
    __syncthreads();

    // ---- input linear: h[n][f] = relu(sum_c x[c*16+n] * w_in[c][f] + b_in[f]) ----
    if (t < 128) {
        int u = t >> 6, f = t & 63;
        float acc[NN];
        #pragma unroll
        for (int n = 0; n < NN; n++) acc[n] = 0.f;
        #pragma unroll
        for (int c = 0; c < 16; c++) {
            float wv = w_in[c * 64 + f];
            #pragma unroll
            for (int n = 0; n < NN; n++)
                acc[n] = fmaf(s.alpha[u][c * 16 + n], wv, acc[n]);
        }
        float bv = b_in[f];
        #pragma unroll
        for (int n = 0; n < NN; n++)
            s.h[u][n * STRIDE + f] = fmaxf(acc[n] + bv, 0.f);
    }
    __syncthreads();

    gat_layer<64,  false>(s, t, W0, as0, ad0, bb0);
    gat_layer<256, false>(s, t, W1, as1, ad1, bb1);
    gat_layer<256, true >(s, t, W2, as2, ad2, bb2);

    // ---- pooled g[c] = mean_i mean_h wh2[i][h][c] + bb2[c] ----
    if (t < 128) {
        int u = t >> 6, c = t & 63;
        float sg = 0.f;
        #pragma unroll
        for (int i = 0; i < NN; i++)
            #pragma unroll
            for (int hh = 0; hh < 4; hh++)
                sg += s.h[u][i * STRIDE + hh * 64 + c];
        s.g[u][c] = sg * (1.0f / 64.0f) + bb2[c];
    }
    __syncthreads();

    // ---- MLP layer 1 (64 -> 128) + LayerNorm + relu ----
    {
        int u = t >> 7, fy = t & 127;
        float v = b1[fy];
        #pragma unroll
        for (int c = 0; c < 64; c++)
            v = fmaf(s.g[u][c], w1[c * 128 + fy], v);

        // two-pass LN over the item's 128 lanes (4 full warps per item)
        float sv = v;
        #pragma unroll
        for (int off = 16; off; off >>= 1)
            sv += __shfl_xor_sync(0xffffffffu, sv, off);
        int wid = t >> 5;
        if ((t & 31) == 0) s.red[u][wid & 3] = sv;
        __syncthreads();
        float mu = (s.red[u][0] + s.red[u][1] + s.red[u][2] + s.red[u][3]) * (1.f / 128.f);
        float d = v - mu;
        float sq = d * d;
        #pragma unroll
        for (int off = 16; off; off >>= 1)
            sq += __shfl_xor_sync(0xffffffffu, sq, off);
        if ((t & 31) == 0) s.red[u][4 + (wid & 3)] = sq;
        __syncthreads();
        float var = (s.red[u][4] + s.red[u][5] + s.red[u][6] + s.red[u][7]) * (1.f / 128.f);
        float yn = d * rsqrtf(var + 1e-5f) * lng[fy] + lnb[fy];
        s.y[u][fy] = fmaxf(yn, 0.f);
    }
    __syncthreads();

    // ---- MLP layer 2 (128 -> 256), write output ----
    {
        float a0 = b2[t], a1 = a0;
        #pragma unroll 8
        for (int f = 0; f < 128; f++) {
            float wv = w2[f * 256 + t];
            a0 = fmaf(s.y[0][f], wv, a0);
            a1 = fmaf(s.y[1][f], wv, a1);
        }
        out[item0 * 256 + t] = a0;
        out[item0 * 256 + 256 + t] = a1;
    }
}

extern "C" void kernel_launch(void* const* d_in, const int* in_sizes, int n_in,
                              void* d_out, int out_size)
{
    const float* x    = (const float*)d_in[0];
    const float* w_in = (const float*)d_in[1];
    const float* b_in = (const float*)d_in[2];
    const float* W0   = (const float*)d_in[3];
    const float* as0  = (const float*)d_in[4];
    const float* ad0  = (const float*)d_in[5];
    const float* bb0  = (const float*)d_in[6];
    const float* W1   = (const float*)d_in[7];
    const float* as1  = (const float*)d_in[8];
    const float* ad1  = (const float*)d_in[9];
    const float* bb1  = (const float*)d_in[10];
    const float* W2   = (const float*)d_in[11];
    const float* as2  = (const float*)d_in[12];
    const float* ad2  = (const float*)d_in[13];
    const float* bb2  = (const float*)d_in[14];
    const float* w1   = (const float*)d_in[15];
    const float* b1   = (const float*)d_in[16];
    const float* lng  = (const float*)d_in[17];
    const float* lnb  = (const float*)d_in[18];
    const float* w2   = (const float*)d_in[19];
    const float* b2   = (const float*)d_in[20];
    float* out = (float*)d_out;

    int B = out_size / 256;          // 16384
    int grid = B / 2;                // 2 graphs per block

    gat_fused_kernel<<<grid, 256>>>(
        x, w_in, b_in,
        W0, as0, ad0, bb0,
        W1, as1, ad1, bb1,
        W2, as2, ad2, bb2,
        w1, b1, lng, lnb, w2, b2,
        out);
}

// round 2
// speedup vs baseline: 1.3356x; 1.3356x over previous
#include <cuda_runtime.h>

// Fused GAT representation network, fp32, LDS-minimized.
// One block of 256 threads processes 2 graphs (16 nodes each) in shared memory.
// Thread mapping for GEMM/aggregation: u = t>>7 (item), h = (t>>5)&3 (head),
// l = t&31; thread owns output columns c0 = h*64+l and c1 = c0+32.

#define NN 16
#define STRIDE 260     // shared row stride in floats (multiple of 4)

__device__ __forceinline__ unsigned adjmask(int i) {
    int r = i >> 2, c = i & 3;
    unsigned m = 1u << i;
    if (c > 0) m |= 1u << (i - 1);
    if (c < 3) m |= 1u << (i + 1);
    if (r > 0) m |= 1u << (i - 4);
    if (r < 3) m |= 1u << (i + 4);
    return m;
}

struct __align__(16) Smem {
    float h[2][NN * STRIDE];     // node features / wh (33280 B)
    float alpha[2][1024];        // alpha[(h*16+i)*16 + j], 16B-aligned rows; x staging
    float esrc[2][NN][4];
    float edst[2][NN][4];
    float g[2][64];
    float y[2][132];
    float red[2][8];
};

template<int FIN, bool FINAL>
__device__ __forceinline__ void gat_layer(
    Smem& s, int t, int u, int h, int l, int c0, int c1,
    const float* __restrict__ W,
    const float* __restrict__ asrc,
    const float* __restrict__ adst,
    const float* __restrict__ bb)
{
    // ---- wh = h @ W : thread owns columns c0, c1 of item u ----
    float acc0[NN], acc1[NN];
    #pragma unroll
    for (int n = 0; n < NN; n++) { acc0[n] = 0.f; acc1[n] = 0.f; }

    #pragma unroll 2
    for (int k = 0; k < FIN; k += 4) {
        float wa0 = W[(k + 0) * 256 + c0];
        float wa1 = W[(k + 1) * 256 + c0];
        float wa2 = W[(k + 2) * 256 + c0];
        float wa3 = W[(k + 3) * 256 + c0];
        float wb0 = W[(k + 0) * 256 + c1];
        float wb1 = W[(k + 1) * 256 + c1];
        float wb2 = W[(k + 2) * 256 + c1];
        float wb3 = W[(k + 3) * 256 + c1];
        #pragma unroll
        for (int n = 0; n < NN; n++) {
            float4 hv = *(const float4*)&s.h[u][n * STRIDE + k];  // broadcast LDS
            acc0[n] = fmaf(hv.x, wa0, fmaf(hv.y, wa1,
                        fmaf(hv.z, wa2, fmaf(hv.w, wa3, acc0[n]))));
            acc1[n] = fmaf(hv.x, wb0, fmaf(hv.y, wb1,
                        fmaf(hv.z, wb2, fmaf(hv.w, wb3, acc1[n]))));
        }
    }
    __syncthreads();
    #pragma unroll
    for (int n = 0; n < NN; n++) {
        s.h[u][n * STRIDE + c0] = acc0[n];
        s.h[u][n * STRIDE + c1] = acc1[n];
    }
    __syncthreads();

    // ---- per-(node, head) logits e_src, e_dst (128 threads) ----
    if (t < 128) {
        int uu = t >> 6, id = t & 63, n = id & 15, hh = id >> 4;
        float as = 0.f, ad = 0.f;
        #pragma unroll
        for (int c = 0; c < 64; c += 4) {
            float4 v = *(const float4*)&s.h[uu][n * STRIDE + hh * 64 + c];
            float4 av = *(const float4*)&asrc[hh * 64 + c];
            float4 dv = *(const float4*)&adst[hh * 64 + c];
            as = fmaf(v.x, av.x, fmaf(v.y, av.y, fmaf(v.z, av.z, fmaf(v.w, av.w, as))));
            ad = fmaf(v.x, dv.x, fmaf(v.y, dv.y, fmaf(v.z, dv.z, fmaf(v.w, dv.w, ad))));
        }
        s.esrc[uu][n][hh] = as;
        s.edst[uu][n][hh] = ad;
    }
    __syncthreads();

    // ---- masked softmax over sources (128 threads: one per (u, i, h)) ----
    if (t < 128) {
        int uu = t >> 6, id = t & 63, i = id & 15, hh = id >> 4;
        unsigned m = adjmask(i);
        float ed = s.edst[uu][i][hh];
        float eb[NN];
        float mx = -1e30f;
        #pragma unroll
        for (int j = 0; j < NN; j++) {
            eb[j] = -1e30f;
            if ((m >> j) & 1u) {
                float e = ed + s.esrc[uu][j][hh];
                e = e > 0.f ? e : 0.2f * e;
                eb[j] = e;
                mx = fmaxf(mx, e);
            }
        }
        float ssum = 0.f;
        #pragma unroll
        for (int j = 0; j < NN; j++) {
            float a = ((m >> j) & 1u) ? __expf(eb[j] - mx) : 0.f;
            eb[j] = a;
            ssum += a;
        }
        float inv = 1.f / ssum;
        #pragma unroll
        for (int j = 0; j < NN; j++)
            s.alpha[uu][(hh * 16 + i) * 16 + j] = eb[j] * inv;
    }
    __syncthreads();

    // ---- aggregation: out[i][c] = sum_j alpha[h][i][j] * wh[j][c] ----
    float o0[NN], o1[NN];
    #pragma unroll
    for (int i = 0; i < NN; i++) { o0[i] = 0.f; o1[i] = 0.f; }

    #pragma unroll
    for (int j4 = 0; j4 < 4; j4++) {
        float wv0[4], wv1[4];
        #pragma unroll
        for (int jj = 0; jj < 4; jj++) {
            int j = j4 * 4 + jj;
            wv0[jj] = s.h[u][j * STRIDE + c0];
            wv1[jj] = s.h[u][j * STRIDE + c1];
        }
        #pragma unroll
        for (int i = 0; i < NN; i++) {
            float4 a4 = *(const float4*)&s.alpha[u][(h * 16 + i) * 16 + j4 * 4]; // broadcast
            o0[i] = fmaf(a4.x, wv0[0], fmaf(a4.y, wv0[1],
                      fmaf(a4.z, wv0[2], fmaf(a4.w, wv0[3], o0[i]))));
            o1[i] = fmaf(a4.x, wv1[0], fmaf(a4.y, wv1[1],
                      fmaf(a4.z, wv1[2], fmaf(a4.w, wv1[3], o1[i]))));
        }
    }
    __syncthreads();
    if (FINAL) {
        #pragma unroll
        for (int i = 0; i < NN; i++) {
            s.h[u][i * STRIDE + c0] = o0[i];
            s.h[u][i * STRIDE + c1] = o1[i];
        }
    } else {
        float bv0 = bb[c0], bv1 = bb[c1];
        #pragma unroll
        for (int i = 0; i < NN; i++) {
            s.h[u][i * STRIDE + c0] = fmaxf(o0[i] + bv0, 0.f);
            s.h[u][i * STRIDE + c1] = fmaxf(o1[i] + bv1, 0.f);
        }
    }
    __syncthreads();
}

__global__ void __launch_bounds__(256, 2) gat_fused_kernel(
    const float* __restrict__ x,
    const float* __restrict__ w_in, const float* __restrict__ b_in,
    const float* __restrict__ W0, const float* __restrict__ as0,
    const float* __restrict__ ad0, const float* __restrict__ bb0,
    const float* __restrict__ W1, const float* __restrict__ as1,
    const float* __restrict__ ad1, const float* __restrict__ bb1,
    const float* __restrict__ W2, const float* __restrict__ as2,
    const float* __restrict__ ad2, const float* __restrict__ bb2,
    const float* __restrict__ w1, const float* __restrict__ b1,
    const float* __restrict__ lng, const float* __restrict__ lnb,
    const float* __restrict__ w2, const float* __restrict__ b2,
    float* __restrict__ out)
{
    __shared__ Smem s;
    int t = threadIdx.x;
    int u = t >> 7;             // item within block
    int h = (t >> 5) & 3;       // head
    int l = t & 31;             // lane within head
    int c0 = h * 64 + l;
    int c1 = c0 + 32;
    long item0 = (long)blockIdx.x * 2;

    // ---- stage x (2 graphs * 256 floats) into alpha scratch ----
    s.alpha[0][t] = x[item0 * 256 + t];
    s.alpha[1][t] = x[item0 * 256 + 256 + t];
    __syncthreads();

    // ---- input linear: h[n][f] = relu(sum_c x[c*16+n] * w_in[c][f] + b_in[f]) ----
    if (t < 128) {
        int uu = t >> 6, f = t & 63;
        float acc[NN];
        #pragma unroll
        for (int n = 0; n < NN; n++) acc[n] = 0.f;
        #pragma unroll
        for (int c = 0; c < 16; c++) {
            float wv = w_in[c * 64 + f];
            #pragma unroll
            for (int n = 0; n < NN; n++)
                acc[n] = fmaf(s.alpha[uu][c * 16 + n], wv, acc[n]);
        }
        float bv = b_in[f];
        #pragma unroll
        for (int n = 0; n < NN; n++)
            s.h[uu][n * STRIDE + f] = fmaxf(acc[n] + bv, 0.f);
    }
    __syncthreads();

    gat_layer<64,  false>(s, t, u, h, l, c0, c1, W0, as0, ad0, bb0);
    gat_layer<256, false>(s, t, u, h, l, c0, c1, W1, as1, ad1, bb1);
    gat_layer<256, true >(s, t, u, h, l, c0, c1, W2, as2, ad2, bb2);

    // ---- pooled g[c] = mean_{i,h} wh2[i][h][c] + bb2[c] ----
    if (t < 128) {
        int uu = t >> 6, c = t & 63;
        float sg = 0.f;
        #pragma unroll
        for (int i = 0; i < NN; i++) {
            #pragma unroll
            for (int hh = 0; hh < 4; hh++)
                sg += s.h[uu][i * STRIDE + hh * 64 + c];
        }
        s.g[uu][c] = sg * (1.0f / 64.0f) + bb2[c];
    }
    __syncthreads();

    // ---- MLP layer 1 (64 -> 128) + LayerNorm + relu ----
    {
        int uu = t >> 7, fy = t & 127;
        float v = b1[fy];
        #pragma unroll
        for (int c = 0; c < 64; c++)
            v = fmaf(s.g[uu][c], w1[c * 128 + fy], v);

        float sv = v;
        #pragma unroll
        for (int off = 16; off; off >>= 1)
            sv += __shfl_xor_sync(0xffffffffu, sv, off);
        int wid = t >> 5;
        if ((t & 31) == 0) s.red[uu][wid & 3] = sv;
        __syncthreads();
        float mu = (s.red[uu][0] + s.red[uu][1] + s.red[uu][2] + s.red[uu][3]) * (1.f / 128.f);
        float d = v - mu;
        float sq = d * d;
        #pragma unroll
        for (int off = 16; off; off >>= 1)
            sq += __shfl_xor_sync(0xffffffffu, sq, off);
        if ((t & 31) == 0) s.red[uu][4 + (wid & 3)] = sq;
        __syncthreads();
        float var = (s.red[uu][4] + s.red[uu][5] + s.red[uu][6] + s.red[uu][7]) * (1.f / 128.f);
        float yn = d * rsqrtf(var + 1e-5f) * lng[fy] + lnb[fy];
        s.y[uu][fy] = fmaxf(yn, 0.f);
    }
    __syncthreads();

    // ---- MLP layer 2 (128 -> 256), write output ----
    {
        float a0 = b2[t], a1 = a0;
        #pragma unroll 4
        for (int f = 0; f < 128; f += 4) {
            float4 y0 = *(const float4*)&s.y[0][f];   // broadcast
            float4 y1 = *(const float4*)&s.y[1][f];
            float w0 = w2[(f + 0) * 256 + t];
            float w1v = w2[(f + 1) * 256 + t];
            float w2v = w2[(f + 2) * 256 + t];
            float w3 = w2[(f + 3) * 256 + t];
            a0 = fmaf(y0.x, w0, fmaf(y0.y, w1v, fmaf(y0.z, w2v, fmaf(y0.w, w3, a0))));
            a1 = fmaf(y1.x, w0, fmaf(y1.y, w1v, fmaf(y1.z, w2v, fmaf(y1.w, w3, a1))));
        }
        out[item0 * 256 + t] = a0;
        out[item0 * 256 + 256 + t] = a1;
    }
}

extern "C" void kernel_launch(void* const* d_in, const int* in_sizes, int n_in,
                              void* d_out, int out_size)
{
    const float* x    = (const float*)d_in[0];
    const float* w_in = (const float*)d_in[1];
    const float* b_in = (const float*)d_in[2];
    const float* W0   = (const float*)d_in[3];
    const float* as0  = (const float*)d_in[4];
    const float* ad0  = (const float*)d_in[5];
    const float* bb0  = (const float*)d_in[6];
    const float* W1   = (const float*)d_in[7];
    const float* as1  = (const float*)d_in[8];
    const float* ad1  = (const float*)d_in[9];
    const float* bb1  = (const float*)d_in[10];
    const float* W2   = (const float*)d_in[11];
    const float* as2  = (const float*)d_in[12];
    const float* ad2  = (const float*)d_in[13];
    const float* bb2  = (const float*)d_in[14];
    const float* w1   = (const float*)d_in[15];
    const float* b1   = (const float*)d_in[16];
    const float* lng  = (const float*)d_in[17];
    const float* lnb  = (const float*)d_in[18];
    const float* w2   = (const float*)d_in[19];
    const float* b2   = (const float*)d_in[20];
    float* out = (float*)d_out;

    int B = out_size / 256;
    int grid = B / 2;

    gat_fused_kernel<<<grid, 256>>>(
        x, w_in, b_in,
        W0, as0, ad0, bb0,
        W1, as1, ad1, bb1,
        W2, as2, ad2, bb2,
        w1, b1, lng, lnb, w2, b2,
        out);
}

// round 3
// speedup vs baseline: 1.5802x; 1.1832x over previous
#include <cuda_runtime.h>

// Fused GAT representation network, fp32x2 packed-FMA version.
// 4 graphs per 256-thread block; features stored transposed in shared:
// hT[item][feature][node] with row stride HS=20 floats.
// GEMM/aggregation thread mapping: u = t>>6 (item), v = t&63,
// thread owns columns 4v..4v+3 (all within head hq = v>>4).

#define NN 16
#define HS 20   // hT row stride in floats (multiple of 4)

// shared-memory float offsets
#define OFF_HT    0                     // [4][256][HS]
#define SZ_HT     (4 * 256 * HS)        // 20480
#define OFF_AL    (OFF_HT + SZ_HT)      // alpha [4][4][16][16]; also x staging
#define SZ_AL     (4 * 1024)
#define OFF_ES    (OFF_AL + SZ_AL)      // esrc [4][16][4]
#define OFF_ED    (OFF_ES + 256)        // edst [4][16][4]
#define OFF_G4    (OFF_ED + 256)        // per-head pooled sums [4][4][64]
#define OFF_G     (OFF_G4 + 1024)       // g [4][64]
#define OFF_Y     (OFF_G + 256)         // y [4][132]
#define OFF_RED   (OFF_Y + 4 * 132)     // LN partials [4][8]
#define SMEM_FLOATS (OFF_RED + 32)
#define SMEM_BYTES  (SMEM_FLOATS * 4)

typedef unsigned long long ull;

__device__ __forceinline__ ull pk(float lo, float hi) {
    ull r; asm("mov.b64 %0, {%1,%2};" : "=l"(r) : "f"(lo), "f"(hi)); return r;
}
__device__ __forceinline__ void upk(ull v, float& lo, float& hi) {
    asm("mov.b64 {%0,%1}, %2;" : "=f"(lo), "=f"(hi) : "l"(v));
}
__device__ __forceinline__ void ffma2(ull& d, ull a, ull b) {
    asm("fma.rn.f32x2 %0, %1, %2, %0;" : "+l"(d) : "l"(a), "l"(b));
}

__device__ __forceinline__ unsigned adjmask(int i) {
    int r = i >> 2, c = i & 3;
    unsigned m = 1u << i;
    if (c > 0) m |= 1u << (i - 1);
    if (c < 3) m |= 1u << (i + 1);
    if (r > 0) m |= 1u << (i - 4);
    if (r < 3) m |= 1u << (i + 4);
    return m;
}

template<int FIN, bool FINAL>
__device__ __forceinline__ void gat_layer(
    float* sm, int t, int u, int v,
    const float* __restrict__ W,
    const float* __restrict__ asrc,
    const float* __restrict__ adst,
    const float* __restrict__ bb)
{
    float* hTu = sm + OFF_HT + u * (256 * HS);
    const int c0 = 4 * v;
    const int hq = v >> 4;

    // ---- GEMM: wh[:, c0..c0+3] = h @ W, node pairs packed in f32x2 ----
    ull acc[4][8];
    #pragma unroll
    for (int c = 0; c < 4; c++)
        #pragma unroll
        for (int p = 0; p < 8; p++) acc[c][p] = 0ull;

    #pragma unroll 4
    for (int k = 0; k < FIN; k++) {
        float4 w4 = *(const float4*)&W[k * 256 + c0];
        ull wp0 = pk(w4.x, w4.x), wp1 = pk(w4.y, w4.y);
        ull wp2 = pk(w4.z, w4.z), wp3 = pk(w4.w, w4.w);
        const float* hr = &hTu[k * HS];
        float4 h0 = *(const float4*)&hr[0];
        float4 h1 = *(const float4*)&hr[4];
        float4 h2 = *(const float4*)&hr[8];
        float4 h3 = *(const float4*)&hr[12];
        ull hp[8] = { pk(h0.x,h0.y), pk(h0.z,h0.w), pk(h1.x,h1.y), pk(h1.z,h1.w),
                      pk(h2.x,h2.y), pk(h2.z,h2.w), pk(h3.x,h3.y), pk(h3.z,h3.w) };
        #pragma unroll
        for (int p = 0; p < 8; p++) {
            ffma2(acc[0][p], hp[p], wp0);
            ffma2(acc[1][p], hp[p], wp1);
            ffma2(acc[2][p], hp[p], wp2);
            ffma2(acc[3][p], hp[p], wp3);
        }
    }
    __syncthreads();   // everyone done reading hT
    #pragma unroll
    for (int c = 0; c < 4; c++) {
        #pragma unroll
        for (int p = 0; p < 8; p++) {
            float lo, hi; upk(acc[c][p], lo, hi);
            *(float2*)&hTu[(c0 + c) * HS + 2 * p] = make_float2(lo, hi);
        }
    }
    __syncthreads();

    // ---- logits: one thread per (u, n, hh) ----
    {
        int id = t & 63, n = id & 15, hh = id >> 4;
        float as = 0.f, ad = 0.f;
        #pragma unroll 8
        for (int c = 0; c < 64; c++) {
            float vv = hTu[(hh * 64 + c) * HS + n];
            as = fmaf(vv, asrc[hh * 64 + c], as);
            ad = fmaf(vv, adst[hh * 64 + c], ad);
        }
        sm[OFF_ES + u * 64 + n * 4 + hh] = as;
        sm[OFF_ED + u * 64 + n * 4 + hh] = ad;
    }
    __syncthreads();

    // ---- masked softmax: one thread per (u, i, hh); alpha stored j-major ----
    {
        int id = t & 63, i = id & 15, hh = id >> 4;
        unsigned m = adjmask(i);
        float ed = sm[OFF_ED + u * 64 + i * 4 + hh];
        float eb[NN];
        float mx = -1e30f;
        #pragma unroll
        for (int j = 0; j < NN; j++) {
            eb[j] = -1e30f;
            if ((m >> j) & 1u) {
                float e = ed + sm[OFF_ES + u * 64 + j * 4 + hh];
                e = e > 0.f ? e : 0.2f * e;
                eb[j] = e;
                mx = fmaxf(mx, e);
            }
        }
        float ssum = 0.f;
        #pragma unroll
        for (int j = 0; j < NN; j++) {
            float a = ((m >> j) & 1u) ? __expf(eb[j] - mx) : 0.f;
            eb[j] = a;
            ssum += a;
        }
        float inv = 1.f / ssum;
        #pragma unroll
        for (int j = 0; j < NN; j++)
            sm[OFF_AL + u * 1024 + hh * 256 + j * 16 + i] = eb[j] * inv;
    }
    __syncthreads();

    // ---- aggregation: out[i][c] = sum_j alpha[h][j][i] * wh[j][c] ----
    ull o2[4][8];
    #pragma unroll
    for (int c = 0; c < 4; c++)
        #pragma unroll
        for (int p = 0; p < 8; p++) o2[c][p] = 0ull;

    const float* au = sm + OFF_AL + u * 1024 + hq * 256;
    #pragma unroll
    for (int j = 0; j < NN; j++) {
        float4 a0 = *(const float4*)&au[j * 16 + 0];
        float4 a1 = *(const float4*)&au[j * 16 + 4];
        float4 a2 = *(const float4*)&au[j * 16 + 8];
        float4 a3 = *(const float4*)&au[j * 16 + 12];
        ull ap[8] = { pk(a0.x,a0.y), pk(a0.z,a0.w), pk(a1.x,a1.y), pk(a1.z,a1.w),
                      pk(a2.x,a2.y), pk(a2.z,a2.w), pk(a3.x,a3.y), pk(a3.z,a3.w) };
        #pragma unroll
        for (int c = 0; c < 4; c++) {
            float wv = hTu[(c0 + c) * HS + j];
            ull wp = pk(wv, wv);
            #pragma unroll
            for (int p = 0; p < 8; p++) ffma2(o2[c][p], ap[p], wp);
        }
    }
    __syncthreads();   // everyone done reading hT + alpha

    if (FINAL) {
        // pool over nodes now; cross-head sum after sync
        float cs[4];
        #pragma unroll
        for (int c = 0; c < 4; c++) {
            float s = 0.f;
            #pragma unroll
            for (int p = 0; p < 8; p++) {
                float lo, hi; upk(o2[c][p], lo, hi);
                s += lo + hi;
            }
            cs[c] = s;
        }
        *(float4*)&sm[OFF_G4 + u * 256 + hq * 64 + (c0 & 63)] =
            make_float4(cs[0], cs[1], cs[2], cs[3]);
    } else {
        float4 b4 = *(const float4*)&bb[c0];
        float bbv[4] = { b4.x, b4.y, b4.z, b4.w };
        #pragma unroll
        for (int c = 0; c < 4; c++) {
            #pragma unroll
            for (int p = 0; p < 8; p++) {
                float lo, hi; upk(o2[c][p], lo, hi);
                lo = fmaxf(lo + bbv[c], 0.f);
                hi = fmaxf(hi + bbv[c], 0.f);
                *(float2*)&hTu[(c0 + c) * HS + 2 * p] = make_float2(lo, hi);
            }
        }
    }
    __syncthreads();
}

__global__ void __launch_bounds__(256, 2) gat_fused_kernel(
    const float* __restrict__ x,
    const float* __restrict__ w_in, const float* __restrict__ b_in,
    const float* __restrict__ W0, const float* __restrict__ as0,
    const float* __restrict__ ad0, const float* __restrict__ bb0,
    const float* __restrict__ W1, const float* __restrict__ as1,
    const float* __restrict__ ad1, const float* __restrict__ bb1,
    const float* __restrict__ W2, const float* __restrict__ as2,
    const float* __restrict__ ad2, const float* __restrict__ bb2,
    const float* __restrict__ w1, const float* __restrict__ b1,
    const float* __restrict__ lng, const float* __restrict__ lnb,
    const float* __restrict__ w2, const float* __restrict__ b2,
    float* __restrict__ out)
{
    extern __shared__ float sm[];
    int t = threadIdx.x;
    int u = t >> 6;           // item
    int v = t & 63;
    long item0 = (long)blockIdx.x * 4;

    // ---- stage x (4 graphs * 256 floats) into alpha scratch ----
    #pragma unroll
    for (int q = 0; q < 4; q++)
        sm[OFF_AL + q * 1024 + t] = x[(item0 + q) * 256 + t];
    __syncthreads();

    // ---- input linear -> hT[f][n], one thread per (u, f) ----
    {
        int f = v;
        const float* xs = sm + OFF_AL + u * 1024;
        float* hTu = sm + OFF_HT + u * (256 * HS);
        float acc[NN];
        #pragma unroll
        for (int n = 0; n < NN; n++) acc[n] = 0.f;
        #pragma unroll
        for (int c = 0; c < 16; c++) {
            float wv = w_in[c * 64 + f];
            #pragma unroll
            for (int n = 0; n < NN; n++)
                acc[n] = fmaf(xs[c * 16 + n], wv, acc[n]);
        }
        float bv = b_in[f];
        #pragma unroll
        for (int n = 0; n < NN; n++)
            hTu[f * HS + n] = fmaxf(acc[n] + bv, 0.f);
    }
    __syncthreads();

    gat_layer<64,  false>(sm, t, u, v, W0, as0, ad0, bb0);
    gat_layer<256, false>(sm, t, u, v, W1, as1, ad1, bb1);
    gat_layer<256, true >(sm, t, u, v, W2, as2, ad2, bb2);

    // ---- cross-head pooled g[c], one thread per (u, c) ----
    {
        float sg = sm[OFF_G4 + u * 256 +   0 + v]
                 + sm[OFF_G4 + u * 256 +  64 + v]
                 + sm[OFF_G4 + u * 256 + 128 + v]
                 + sm[OFF_G4 + u * 256 + 192 + v];
        sm[OFF_G + u * 64 + v] = sg * (1.0f / 64.0f) + bb2[v];
    }
    __syncthreads();

    // ---- MLP layer 1 (64->128) + LayerNorm + relu; thread covers 2 items ----
    {
        int fy = t & 127, up = t >> 7;
        int ua = up, ub = up + 2;
        float va = b1[fy], vb = va;
        #pragma unroll 4
        for (int c = 0; c < 64; c += 4) {
            float4 ga = *(const float4*)&sm[OFF_G + ua * 64 + c];
            float4 gb = *(const float4*)&sm[OFF_G + ub * 64 + c];
            float w0 = w1[(c + 0) * 128 + fy];
            float wA = w1[(c + 1) * 128 + fy];
            float wB = w1[(c + 2) * 128 + fy];
            float wC = w1[(c + 3) * 128 + fy];
            va = fmaf(ga.x, w0, fmaf(ga.y, wA, fmaf(ga.z, wB, fmaf(ga.w, wC, va))));
            vb = fmaf(gb.x, w0, fmaf(gb.y, wA, fmaf(gb.z, wB, fmaf(gb.w, wC, vb))));
        }
        float sa = va, sb = vb;
        #pragma unroll
        for (int off = 16; off; off >>= 1) {
            sa += __shfl_xor_sync(0xffffffffu, sa, off);
            sb += __shfl_xor_sync(0xffffffffu, sb, off);
        }
        int wi = (t >> 5) & 3;
        if ((t & 31) == 0) {
            sm[OFF_RED + ua * 8 + wi] = sa;
            sm[OFF_RED + ub * 8 + wi] = sb;
        }
        __syncthreads();
        float mua = (sm[OFF_RED + ua * 8 + 0] + sm[OFF_RED + ua * 8 + 1] +
                     sm[OFF_RED + ua * 8 + 2] + sm[OFF_RED + ua * 8 + 3]) * (1.f / 128.f);
        float mub = (sm[OFF_RED + ub * 8 + 0] + sm[OFF_RED + ub * 8 + 1] +
                     sm[OFF_RED + ub * 8 + 2] + sm[OFF_RED + ub * 8 + 3]) * (1.f / 128.f);
        float da = va - mua, db = vb - mub;
        float qa = da * da, qb = db * db;
        #pragma unroll
        for (int off = 16; off; off >>= 1) {
            qa += __shfl_xor_sync(0xffffffffu, qa, off);
            qb += __shfl_xor_sync(0xffffffffu, qb, off);
        }
        if ((t & 31) == 0) {
            sm[OFF_RED + ua * 8 + 4 + wi] = qa;
            sm[OFF_RED + ub * 8 + 4 + wi] = qb;
        }
        __syncthreads();
        float vara = (sm[OFF_RED + ua * 8 + 4] + sm[OFF_RED + ua * 8 + 5] +
                      sm[OFF_RED + ua * 8 + 6] + sm[OFF_RED + ua * 8 + 7]) * (1.f / 128.f);
        float varb = (sm[OFF_RED + ub * 8 + 4] + sm[OFF_RED + ub * 8 + 5] +
                      sm[OFF_RED + ub * 8 + 6] + sm[OFF_RED + ub * 8 + 7]) * (1.f / 128.f);
        float gv = lng[fy], bv = lnb[fy];
        sm[OFF_Y + ua * 132 + fy] = fmaxf(da * rsqrtf(vara + 1e-5f) * gv + bv, 0.f);
        sm[OFF_Y + ub * 132 + fy] = fmaxf(db * rsqrtf(varb + 1e-5f) * gv + bv, 0.f);
    }
    __syncthreads();

    // ---- MLP layer 2 (128 -> 256), write 4 items ----
    {
        float a0 = b2[t], a1 = a0, a2 = a0, a3 = a0;
        #pragma unroll 4
        for (int f = 0; f < 128; f += 4) {
            float4 y0 = *(const float4*)&sm[OFF_Y + 0 * 132 + f];
            float4 y1 = *(const float4*)&sm[OFF_Y + 1 * 132 + f];
            float4 y2 = *(const float4*)&sm[OFF_Y + 2 * 132 + f];
            float4 y3 = *(const float4*)&sm[OFF_Y + 3 * 132 + f];
            float w0 = w2[(f + 0) * 256 + t];
            float wA = w2[(f + 1) * 256 + t];
            float wB = w2[(f + 2) * 256 + t];
            float wC = w2[(f + 3) * 256 + t];
            a0 = fmaf(y0.x, w0, fmaf(y0.y, wA, fmaf(y0.z, wB, fmaf(y0.w, wC, a0))));
            a1 = fmaf(y1.x, w0, fmaf(y1.y, wA, fmaf(y1.z, wB, fmaf(y1.w, wC, a1))));
            a2 = fmaf(y2.x, w0, fmaf(y2.y, wA, fmaf(y2.z, wB, fmaf(y2.w, wC, a2))));
            a3 = fmaf(y3.x, w0, fmaf(y3.y, wA, fmaf(y3.z, wB, fmaf(y3.w, wC, a3))));
        }
        out[(item0 + 0) * 256 + t] = a0;
        out[(item0 + 1) * 256 + t] = a1;
        out[(item0 + 2) * 256 + t] = a2;
        out[(item0 + 3) * 256 + t] = a3;
    }
}

extern "C" void kernel_launch(void* const* d_in, const int* in_sizes, int n_in,
                              void* d_out, int out_size)
{
    const float* x    = (const float*)d_in[0];
    const float* w_in = (const float*)d_in[1];
    const float* b_in = (const float*)d_in[2];
    const float* W0   = (const float*)d_in[3];
    const float* as0  = (const float*)d_in[4];
    const float* ad0  = (const float*)d_in[5];
    const float* bb0  = (const float*)d_in[6];
    const float* W1   = (const float*)d_in[7];
    const float* as1  = (const float*)d_in[8];
    const float* ad1  = (const float*)d_in[9];
    const float* bb1  = (const float*)d_in[10];
    const float* W2   = (const float*)d_in[11];
    const float* as2  = (const float*)d_in[12];
    const float* ad2  = (const float*)d_in[13];
    const float* bb2  = (const float*)d_in[14];
    const float* w1   = (const float*)d_in[15];
    const float* b1   = (const float*)d_in[16];
    const float* lng  = (const float*)d_in[17];
    const float* lnb  = (const float*)d_in[18];
    const float* w2   = (const float*)d_in[19];
    const float* b2   = (const float*)d_in[20];
    float* out = (float*)d_out;

    int B = out_size / 256;       // 16384
    int grid = B / 4;             // 4 graphs per block

    cudaFuncSetAttribute(gat_fused_kernel,
                         cudaFuncAttributeMaxDynamicSharedMemorySize, SMEM_BYTES);
    gat_fused_kernel<<<grid, 256, SMEM_BYTES>>>(
        x, w_in, b_in,
        W0, as0, ad0, bb0,
        W1, as1, ad1, bb1,
        W2, as2, ad2, bb2,
        w1, b1, lng, lnb, w2, b2,
        out);
}